// round 3
// baseline (speedup 1.0000x reference)
#include <cuda_runtime.h>
#include <stdint.h>

// Problem dims (fixed by the dataset)
#define FDIM 16384   // n_features
#define DDIM 768     // d_model
#define NB   1024    // B*S
#define MCONN 262144 // n_connections

// -------- scratch (device globals; no allocation allowed) --------
__device__ float g_udT[(size_t)FDIM * DDIM];    // up_decoder transposed: [F, D]  (~50 MB)
__device__ float g_XT[(size_t)FDIM * NB];       // up_facts transposed:   [F, NB] (~67 MB)
__device__ float g_values[MCONN];               // per-connection weight value
__device__ int   g_rowstart[FDIM + 1];          // CSR offsets over sorted i_indices
__device__ int   g_j32[MCONN];                  // j indices as int32
__device__ int   g_is64;                        // 1 if index buffers are int64

// ---------------------------------------------------------------
// Detect whether index buffers are int64 or int32.
// View i_indices as int32 words. If underlying dtype is int64 (values
// < 16384, little-endian), every odd word is 0. If int32, the word at
// 2*q+1 is i_indices[2q+1] which, for q=65536 in a sorted array over
// [0,16384), is ~8192 != 0. Check 8 odd words for robustness.
// ---------------------------------------------------------------
__global__ void detect_kernel(const int* __restrict__ raw) {
    if (threadIdx.x == 0 && blockIdx.x == 0) {
        int q = MCONN / 4;   // word index 2*q+1 = 131073 < MCONN (safe either way)
        int odd_nonzero = 0;
        for (int k = 0; k < 8; k++)
            odd_nonzero |= raw[2 * (q + k) + 1];
        g_is64 = odd_nonzero ? 0 : 1;
    }
}

__device__ __forceinline__ int idx_at(const void* p, int is64, int m) {
    return is64 ? (int)((const long long*)p)[m] : ((const int*)p)[m];
}

// ---------------------------------------------------------------
// Tiled transposes into device-global scratch
// ---------------------------------------------------------------
__global__ void transpose_ud_kernel(const float* __restrict__ in) {
    __shared__ float tile[32][33];
    int c0 = blockIdx.x * 32;   // F dimension
    int r0 = blockIdx.y * 32;   // D dimension
    int tx = threadIdx.x, ty = threadIdx.y;   // block (32, 8)
#pragma unroll
    for (int k = 0; k < 32; k += 8)
        tile[ty + k][tx] = in[(size_t)(r0 + ty + k) * FDIM + (c0 + tx)];
    __syncthreads();
#pragma unroll
    for (int k = 0; k < 32; k += 8)
        g_udT[(size_t)(c0 + ty + k) * DDIM + (r0 + tx)] = tile[tx][ty + k];
}

__global__ void transpose_x_kernel(const float* __restrict__ in) {
    __shared__ float tile[32][33];
    int c0 = blockIdx.x * 32;   // F dimension
    int r0 = blockIdx.y * 32;   // NB dimension
    int tx = threadIdx.x, ty = threadIdx.y;
#pragma unroll
    for (int k = 0; k < 32; k += 8)
        tile[ty + k][tx] = in[(size_t)(r0 + ty + k) * FDIM + (c0 + tx)];
    __syncthreads();
#pragma unroll
    for (int k = 0; k < 32; k += 8)
        g_XT[(size_t)(c0 + ty + k) * NB + (r0 + tx)] = tile[tx][ty + k];
}

// ---------------------------------------------------------------
// CSR row offsets over sorted i_indices + j conversion to int32
// ---------------------------------------------------------------
__global__ void csr_kernel(const void* __restrict__ ii) {
    int i = blockIdx.x * blockDim.x + threadIdx.x;
    if (i > FDIM) return;
    int is64 = g_is64;
    int lo = 0, hi = MCONN;
    while (lo < hi) {
        int mid = (lo + hi) >> 1;
        if (idx_at(ii, is64, mid) < i) lo = mid + 1;
        else hi = mid;
    }
    g_rowstart[i] = lo;
}

__global__ void jconv_kernel(const void* __restrict__ jj) {
    int m = blockIdx.x * blockDim.x + threadIdx.x;
    if (m < MCONN) g_j32[m] = idx_at(jj, g_is64, m);
}

// ---------------------------------------------------------------
// Phase A: values[m] = <down_encoder[i_m,:], udT[j_m,:]>
// One warp per i-group; down_encoder row cached in registers.
// ---------------------------------------------------------------
__global__ __launch_bounds__(256) void values_kernel(const float* __restrict__ de) {
    int warp = (blockIdx.x * blockDim.x + threadIdx.x) >> 5;
    int lane = threadIdx.x & 31;
    if (warp >= FDIM) return;
    int i = warp;
    int s = g_rowstart[i];
    int e = g_rowstart[i + 1];
    if (s == e) return;

    // Cache de[i, :] in registers: 24 floats/lane as 6 float4
    float4 a[6];
    const float4* dev = (const float4*)(de + (size_t)i * DDIM);
#pragma unroll
    for (int k = 0; k < 6; k++) a[k] = dev[lane + 32 * k];

    for (int m = s; m < e; m++) {
        int j = g_j32[m];
        const float4* u = (const float4*)(g_udT + (size_t)j * DDIM);
        float sum = 0.f;
#pragma unroll
        for (int k = 0; k < 6; k++) {
            float4 b = u[lane + 32 * k];
            sum += a[k].x * b.x + a[k].y * b.y + a[k].z * b.z + a[k].w * b.w;
        }
#pragma unroll
        for (int o = 16; o; o >>= 1) sum += __shfl_xor_sync(0xffffffffu, sum, o);
        if (lane == 0) g_values[m] = sum;
    }
}

// ---------------------------------------------------------------
// Phase B: SpMM. out[n, i] = sum_{m in group(i)} values[m] * XT[j_m, n]
// Tile: ITILE=32 rows (i) x NTILE=256 cols (n), register accumulators.
// ---------------------------------------------------------------
#define ITILE 32
#define NTILE 256
#define CHUNK 1024

__global__ __launch_bounds__(NTILE) void spmm_kernel(float* __restrict__ out) {
    __shared__ int   sj[CHUNK];
    __shared__ float sv[CHUNK];
    __shared__ int   soff[ITILE + 1];

    int i0 = blockIdx.x * ITILE;
    int n  = blockIdx.y * NTILE + threadIdx.x;

    if (threadIdx.x <= ITILE) soff[threadIdx.x] = g_rowstart[i0 + threadIdx.x];
    __syncthreads();

    int mbase = soff[0];
    int mend  = soff[ITILE];

    float acc[ITILE];
#pragma unroll
    for (int k = 0; k < ITILE; k++) acc[k] = 0.f;

    for (int cb = mbase; cb < mend; cb += CHUNK) {
        int cend = min(cb + CHUNK, mend);
        __syncthreads();
        for (int t = cb + threadIdx.x; t < cend; t += NTILE) {
            sj[t - cb] = g_j32[t];
            sv[t - cb] = g_values[t];
        }
        __syncthreads();
#pragma unroll
        for (int il = 0; il < ITILE; il++) {
            int ms = max(soff[il], cb);
            int me = min(soff[il + 1], cend);
            for (int m = ms; m < me; m++) {
                float v = sv[m - cb];
                float x = g_XT[(size_t)sj[m - cb] * NB + n];
                acc[il] += v * x;
            }
        }
    }

    // Write 32 contiguous outputs for this n (8 x float4, full sectors)
    float4* o = (float4*)(out + (size_t)n * FDIM + i0);
#pragma unroll
    for (int k = 0; k < 8; k++)
        o[k] = make_float4(acc[4 * k + 0], acc[4 * k + 1],
                           acc[4 * k + 2], acc[4 * k + 3]);
}

// ---------------------------------------------------------------
extern "C" void kernel_launch(void* const* d_in, const int* in_sizes, int n_in,
                              void* d_out, int out_size) {
    const float* up_facts = (const float*)d_in[0];   // [B,S,F] = [NB, F]
    const float* down_enc = (const float*)d_in[1];   // [F, D]
    const float* up_dec   = (const float*)d_in[2];   // [D, F]
    const void*  ii       = d_in[3];                 // [M] sorted (int32 or int64)
    const void*  jj       = d_in[4];                 // [M]       (int32 or int64)
    float* out = (float*)d_out;                      // [NB, F]

    dim3 tb(32, 8);
    // dtype detection for index buffers
    detect_kernel<<<1, 32>>>((const int*)ii);
    // up_decoder [D, F] -> g_udT [F, D]
    transpose_ud_kernel<<<dim3(FDIM / 32, DDIM / 32), tb>>>(up_dec);
    // up_facts [NB, F] -> g_XT [F, NB]
    transpose_x_kernel<<<dim3(FDIM / 32, NB / 32), tb>>>(up_facts);
    // CSR offsets + j32
    csr_kernel<<<(FDIM + 1 + 255) / 256, 256>>>(ii);
    jconv_kernel<<<MCONN / 256, 256>>>(jj);
    // Phase A: connection values (warp per i-group; 8 warps/block)
    values_kernel<<<FDIM / 8, 256>>>(down_enc);
    // Phase B: SpMM into d_out
    spmm_kernel<<<dim3(FDIM / ITILE, NB / NTILE), NTILE>>>(out);
}

// round 4
// speedup vs baseline: 1.4602x; 1.4602x over previous
#include <cuda_runtime.h>
#include <cuda_fp16.h>
#include <stdint.h>

// Problem dims (fixed by the dataset)
#define FDIM 16384   // n_features
#define DDIM 768     // d_model
#define NB   1024    // B*S
#define MCONN 262144 // n_connections

// -------- scratch (device globals; no allocation allowed) --------
__device__ __half g_udTh[(size_t)FDIM * DDIM]; // up_decoder^T in fp16: [F, D] (~25 MB)
__device__ __half g_XTh[(size_t)FDIM * NB];    // up_facts^T in fp16:   [F, NB] (~33 MB)
__device__ float  g_values[MCONN];             // per-connection weight value (fp32)
__device__ int    g_rowstart[FDIM + 1];        // CSR offsets over sorted i_indices
__device__ int    g_j32[MCONN];                // j indices as int32
__device__ int    g_is64;                      // 1 if index buffers are int64

// ---------------------------------------------------------------
// Detect whether index buffers are int64 or int32 (values < 16384:
// odd int32-words of an int64 array are all zero; for int32 data the
// probed words are sorted indices ~8192 != 0).
// ---------------------------------------------------------------
__global__ void detect_kernel(const int* __restrict__ raw) {
    if (threadIdx.x == 0 && blockIdx.x == 0) {
        int q = MCONN / 4;
        int odd_nonzero = 0;
        for (int k = 0; k < 8; k++)
            odd_nonzero |= raw[2 * (q + k) + 1];
        g_is64 = odd_nonzero ? 0 : 1;
    }
}

__device__ __forceinline__ int idx_at(const void* p, int is64, int m) {
    return is64 ? (int)((const long long*)p)[m] : ((const int*)p)[m];
}

// ---------------------------------------------------------------
// Tiled transposes into fp16 device-global scratch
// ---------------------------------------------------------------
__global__ void transpose_ud_kernel(const float* __restrict__ in) {
    __shared__ float tile[32][33];
    int c0 = blockIdx.x * 32;   // F dimension
    int r0 = blockIdx.y * 32;   // D dimension
    int tx = threadIdx.x, ty = threadIdx.y;   // block (32, 8)
#pragma unroll
    for (int k = 0; k < 32; k += 8)
        tile[ty + k][tx] = in[(size_t)(r0 + ty + k) * FDIM + (c0 + tx)];
    __syncthreads();
#pragma unroll
    for (int k = 0; k < 32; k += 8)
        g_udTh[(size_t)(c0 + ty + k) * DDIM + (r0 + tx)] = __float2half(tile[tx][ty + k]);
}

__global__ void transpose_x_kernel(const float* __restrict__ in) {
    __shared__ float tile[32][33];
    int c0 = blockIdx.x * 32;   // F dimension
    int r0 = blockIdx.y * 32;   // NB dimension
    int tx = threadIdx.x, ty = threadIdx.y;
#pragma unroll
    for (int k = 0; k < 32; k += 8)
        tile[ty + k][tx] = in[(size_t)(r0 + ty + k) * FDIM + (c0 + tx)];
    __syncthreads();
#pragma unroll
    for (int k = 0; k < 32; k += 8)
        g_XTh[(size_t)(c0 + ty + k) * NB + (r0 + tx)] = __float2half(tile[tx][ty + k]);
}

// ---------------------------------------------------------------
// CSR row offsets via O(M) scatter over the sorted i array.
// rowstart[i] = first m with ii[m] >= i.
// ---------------------------------------------------------------
__global__ void csr_scatter_kernel(const void* __restrict__ ii) {
    int m = blockIdx.x * blockDim.x + threadIdx.x;
    if (m >= MCONN) return;
    int is64 = g_is64;
    int cur = idx_at(ii, is64, m);
    int prev = (m == 0) ? -1 : idx_at(ii, is64, m - 1);
    for (int i = prev + 1; i <= cur; i++) g_rowstart[i] = m;
    if (m == MCONN - 1)
        for (int i = cur + 1; i <= FDIM; i++) g_rowstart[i] = MCONN;
}

__global__ void jconv_kernel(const void* __restrict__ jj) {
    int m = blockIdx.x * blockDim.x + threadIdx.x;
    if (m < MCONN) g_j32[m] = idx_at(jj, g_is64, m);
}

// ---------------------------------------------------------------
// Phase A: values[m] = <down_encoder[i_m,:], udT[j_m,:]> (fp16 gather,
// fp32 accumulate). One warp per i-group; de row cached in registers.
// Lane element coverage: positions (lane+32k)*8 .. +7 for k<3.
// ---------------------------------------------------------------
__global__ __launch_bounds__(256) void values_kernel(const float* __restrict__ de) {
    int warp = (blockIdx.x * blockDim.x + threadIdx.x) >> 5;
    int lane = threadIdx.x & 31;
    if (warp >= FDIM) return;
    int i = warp;
    int s = g_rowstart[i];
    int e = g_rowstart[i + 1];
    if (s == e) return;

    // Cache de[i, :] lane-slice in registers: 24 floats = 6 float4
    float a[3][8];
    const float4* dev = (const float4*)(de + (size_t)i * DDIM);
#pragma unroll
    for (int k = 0; k < 3; k++) {
        float4 p = dev[2 * lane + 64 * k];
        float4 q = dev[2 * lane + 64 * k + 1];
        a[k][0] = p.x; a[k][1] = p.y; a[k][2] = p.z; a[k][3] = p.w;
        a[k][4] = q.x; a[k][5] = q.y; a[k][6] = q.z; a[k][7] = q.w;
    }

    for (int m = s; m < e; m++) {
        int j = g_j32[m];
        const uint4* u = (const uint4*)(g_udTh + (size_t)j * DDIM);
        float sum = 0.f;
#pragma unroll
        for (int k = 0; k < 3; k++) {
            uint4 b = u[lane + 32 * k];
            const __half2* h = (const __half2*)&b;
#pragma unroll
            for (int t = 0; t < 4; t++) {
                float2 f = __half22float2(h[t]);
                sum += a[k][2 * t] * f.x + a[k][2 * t + 1] * f.y;
            }
        }
#pragma unroll
        for (int o = 16; o; o >>= 1) sum += __shfl_xor_sync(0xffffffffu, sum, o);
        if (lane == 0) g_values[m] = sum;
    }
}

// ---------------------------------------------------------------
// Phase B: SpMM. out[n, i] = sum_{m in group(i)} values[m] * XT[j_m, n]
// Block: 256 threads; each thread handles 2 consecutive n (half2 load).
// Tile: ITILE=16 i-rows x 512 n-cols.
// ---------------------------------------------------------------
#define ITILE 16
#define NTHR  256
#define NCOLS 512
#define CHUNK 512

__global__ __launch_bounds__(NTHR) void spmm_kernel(float* __restrict__ out) {
    __shared__ int   sj[CHUNK];
    __shared__ float sv[CHUNK];
    __shared__ int   soff[ITILE + 1];

    int i0 = blockIdx.x * ITILE;
    int n0 = blockIdx.y * NCOLS + threadIdx.x * 2;   // two consecutive n per thread

    if (threadIdx.x <= ITILE) soff[threadIdx.x] = g_rowstart[i0 + threadIdx.x];
    __syncthreads();

    int mbase = soff[0];
    int mend  = soff[ITILE];

    float2 acc[ITILE];
#pragma unroll
    for (int k = 0; k < ITILE; k++) acc[k] = make_float2(0.f, 0.f);

    for (int cb = mbase; cb < mend; cb += CHUNK) {
        int cend = min(cb + CHUNK, mend);
        __syncthreads();
        for (int t = cb + threadIdx.x; t < cend; t += NTHR) {
            sj[t - cb] = g_j32[t];
            sv[t - cb] = g_values[t];
        }
        __syncthreads();
#pragma unroll
        for (int il = 0; il < ITILE; il++) {
            int ms = max(soff[il], cb);
            int me = min(soff[il + 1], cend);
            for (int m = ms; m < me; m++) {
                float v = sv[m - cb];
                __half2 h = *(const __half2*)(g_XTh + (size_t)sj[m - cb] * NB + n0);
                float2 f = __half22float2(h);
                acc[il].x += v * f.x;
                acc[il].y += v * f.y;
            }
        }
    }

    // Write 16 contiguous outputs for each of the two n rows (4 float4 each)
    float4* o0 = (float4*)(out + (size_t)n0 * FDIM + i0);
    float4* o1 = (float4*)(out + (size_t)(n0 + 1) * FDIM + i0);
#pragma unroll
    for (int k = 0; k < 4; k++) {
        o0[k] = make_float4(acc[4 * k].x, acc[4 * k + 1].x, acc[4 * k + 2].x, acc[4 * k + 3].x);
        o1[k] = make_float4(acc[4 * k].y, acc[4 * k + 1].y, acc[4 * k + 2].y, acc[4 * k + 3].y);
    }
}

// ---------------------------------------------------------------
extern "C" void kernel_launch(void* const* d_in, const int* in_sizes, int n_in,
                              void* d_out, int out_size) {
    const float* up_facts = (const float*)d_in[0];   // [B,S,F] = [NB, F]
    const float* down_enc = (const float*)d_in[1];   // [F, D]
    const float* up_dec   = (const float*)d_in[2];   // [D, F]
    const void*  ii       = d_in[3];                 // [M] sorted (int32 or int64)
    const void*  jj       = d_in[4];                 // [M]
    float* out = (float*)d_out;                      // [NB, F]

    dim3 tb(32, 8);
    detect_kernel<<<1, 32>>>((const int*)ii);
    // up_decoder [D, F] -> g_udTh [F, D] fp16
    transpose_ud_kernel<<<dim3(FDIM / 32, DDIM / 32), tb>>>(up_dec);
    // up_facts [NB, F] -> g_XTh [F, NB] fp16
    transpose_x_kernel<<<dim3(FDIM / 32, NB / 32), tb>>>(up_facts);
    // CSR offsets (O(M) scatter) + j32
    csr_scatter_kernel<<<MCONN / 256, 256>>>(ii);
    jconv_kernel<<<MCONN / 256, 256>>>(jj);
    // Phase A: connection values (warp per i-group)
    values_kernel<<<FDIM / 8, 256>>>(down_enc);
    // Phase B: SpMM into d_out
    spmm_kernel<<<dim3(FDIM / ITILE, NB / NCOLS), NTHR>>>(out);
}